// round 16
// baseline (speedup 1.0000x reference)
#include <cuda_runtime.h>
#include <cuda_bf16.h>
#include <cstdint>

// ---------------- problem constants (fixed shapes) ----------------
#define B_   4
#define HH   56
#define WW   56
#define C_   96
#define L_   (HH*WW)          // 3136
#define NH   3
#define HD   32
#define WS   7
#define SS   3
#define NWIN 64
#define BW   (B_*NWIN)        // 256
#define NW2  (WS*WS)          // 49
#define NTOK (B_*L_)          // 12544
#define C3   (3*C_)           // 288
#define C4   (4*C_)           // 384

typedef unsigned long long ull;
typedef __nv_bfloat16 bf16;

// ---------------- scratch (device globals; zero-init, no runtime alloc) ------
__device__ bf16  g_xw   [NTOK*C_];
__device__ bf16  g_qkvw [NTOK*C3];
__device__ bf16  g_attnw[NTOK*C_];
__device__ float g_x1   [NTOK*C_];
__device__ bf16  g_y    [NTOK*C_];
__device__ bf16  g_qkv2 [NTOK*C3];
__device__ bf16  g_ao   [NTOK*C_];
__device__ float g_x2   [NTOK*C_];
__device__ bf16  g_h1   [NTOK*C4];
__device__ bf16  g_wbf  [147456];     // all six weight matrices, bf16

// weight arena offsets
#define W_QKV  0
#define W_PROJ 27648
#define W_QKV2 36864
#define W_OUT  64512
#define W_FC1  73728
#define W_FC2  110592

// ---------------- packed f32x2 helpers ----------------
__device__ __forceinline__ ull ffma2(ull a, ull b, ull c) {
    ull d; asm("fma.rn.f32x2 %0,%1,%2,%3;" : "=l"(d) : "l"(a), "l"(b), "l"(c)); return d;
}
__device__ __forceinline__ ull fadd2(ull a, ull b) {
    ull d; asm("add.rn.f32x2 %0,%1,%2;" : "=l"(d) : "l"(a), "l"(b)); return d;
}
__device__ __forceinline__ ull fmul2(ull a, ull b) {
    ull d; asm("mul.rn.f32x2 %0,%1,%2;" : "=l"(d) : "l"(a), "l"(b)); return d;
}
__device__ __forceinline__ ull dup2(float a) {
    ull r; asm("mov.b64 %0,{%1,%1};" : "=l"(r) : "f"(a)); return r;
}
__device__ __forceinline__ void upk2(ull x, float& a, float& b) {
    asm("mov.b64 {%0,%1},%2;" : "=f"(a), "=f"(b) : "l"(x));
}
__device__ __forceinline__ ull pack2(float lo, float hi) {
    ull r; asm("mov.b64 %0,{%1,%2};" : "=l"(r) : "f"(lo), "f"(hi)); return r;
}
#define ULL2(x) ((((ull)(x)) << 32) | (ull)(x))

// packed exp with FOLDED scale: returns exp(s * K) where C2 = dup2(K*log2e),
// NC2 = dup2(-K*log2e). Negated-f formulation, 4-term poly (rel err <= 4.2e-5).
__device__ __forceinline__ ull fexp2pk_c(ull s2, ull C2, ull NC2) {
    const ull MAG  = ULL2(0x4B400000u);
    const ull NMAG = ULL2(0xCB400000u);
    ull y2 = ffma2(s2, C2, MAG);
    ull r2 = fadd2(y2, NMAG);
    ull f2 = ffma2(s2, NC2, r2);
    ull p2 = ffma2(dup2(0.0096181292f), f2, dup2(-0.0555041087f));
    p2 = ffma2(p2, f2, dup2(0.2402265070f));
    p2 = ffma2(p2, f2, dup2(-0.6931471806f));
    p2 = ffma2(p2, f2, dup2(1.0f));
    unsigned ylo = (unsigned)y2, yhi = (unsigned)(y2 >> 32);
    unsigned slo = (ylo + 0xB4C0007Fu) << 23;
    unsigned shi = (yhi + 0xB4C0007Fu) << 23;
    return fmul2(p2, ((ull)shi << 32) | (ull)slo);
}

__device__ __forceinline__ float wred(float v) {
    #pragma unroll
    for (int o = 16; o > 0; o >>= 1) v += __shfl_xor_sync(0xffffffffu, v, o);
    return v;
}

// ---------------- mma.sync / ldmatrix primitives ----------------
__device__ __forceinline__ uint32_t smem_to_u32(const void* p) {
    uint32_t a;
    asm("{ .reg .u64 t; cvta.to.shared.u64 t, %1; cvt.u32.u64 %0, t; }" : "=r"(a) : "l"(p));
    return a;
}
__device__ __forceinline__ uint32_t cvt_bf16x2(float hi, float lo) {
    uint32_t r; asm("cvt.rn.bf16x2.f32 %0, %1, %2;" : "=r"(r) : "f"(hi), "f"(lo)); return r;
}
__device__ __forceinline__ void mma_bf16(float* c, const uint32_t* a, const uint32_t* b) {
    asm volatile("mma.sync.aligned.m16n8k16.row.col.f32.bf16.bf16.f32 "
        "{%0,%1,%2,%3},{%4,%5,%6,%7},{%8,%9},{%0,%1,%2,%3};"
        : "+f"(c[0]), "+f"(c[1]), "+f"(c[2]), "+f"(c[3])
        : "r"(a[0]), "r"(a[1]), "r"(a[2]), "r"(a[3]), "r"(b[0]), "r"(b[1]));
}
__device__ __forceinline__ void ldsm4(uint32_t* r, uint32_t addr) {
    asm volatile("ldmatrix.sync.aligned.m8n8.x4.shared.b16 {%0,%1,%2,%3},[%4];"
        : "=r"(r[0]), "=r"(r[1]), "=r"(r[2]), "=r"(r[3]) : "r"(addr));
}
__device__ __forceinline__ void ldsm4t(uint32_t* r, uint32_t addr) {
    asm volatile("ldmatrix.sync.aligned.m8n8.x4.trans.shared.b16 {%0,%1,%2,%3},[%4];"
        : "=r"(r[0]), "=r"(r[1]), "=r"(r[2]), "=r"(r[3]) : "r"(addr));
}

// ------- combined: LN1+shift+window partition (blocks 0..1567) ---------------
// -------           weight fp32->bf16 conversion + tail (blocks >= 1568) ------
#define LN1_BLOCKS (NTOK / 8)
__global__ void ln1_wconv_kernel(const float* __restrict__ x,
                                 const float* __restrict__ sc,
                                 const float* __restrict__ bi,
                                 bf16* __restrict__ xw,
                                 const float* __restrict__ a0, const float* __restrict__ a1,
                                 const float* __restrict__ a2, const float* __restrict__ a3,
                                 const float* __restrict__ a4, const float* __restrict__ a5,
                                 bf16* __restrict__ wdst,
                                 float* __restrict__ out, int out_size) {
    if (blockIdx.x >= LN1_BLOCKS) {
        if (blockIdx.x == LN1_BLOCKS) {
            int ti = NTOK * C_ + (int)threadIdx.x;
            if (ti < out_size) out[ti] = 56.0f;
        }
        int i = (blockIdx.x - LN1_BLOCKS) * 256 + threadIdx.x;
        if (i >= 147456) return;
        const float* src; int off;
        if      (i < W_PROJ) { src = a0; off = W_QKV;  }
        else if (i < W_QKV2) { src = a1; off = W_PROJ; }
        else if (i < W_OUT)  { src = a2; off = W_QKV2; }
        else if (i < W_FC1)  { src = a3; off = W_OUT;  }
        else if (i < W_FC2)  { src = a4; off = W_FC1;  }
        else                 { src = a5; off = W_FC2;  }
        wdst[i] = __float2bfloat16(src[i - off]);
        return;
    }
    int warp = (blockIdx.x * blockDim.x + threadIdx.x) >> 5;
    int lane = threadIdx.x & 31;
    const float* row = x + (size_t)warp * C_;
    float v0 = row[lane], v1 = row[lane + 32], v2 = row[lane + 64];
    float mean = wred(v0 + v1 + v2) * (1.0f / C_);
    float d0 = v0 - mean, d1 = v1 - mean, d2 = v2 - mean;
    float var = wred(d0*d0 + d1*d1 + d2*d2) * (1.0f / C_);
    float inv = rsqrtf(var + 1e-6f);
    int b = warp / L_, l = warp % L_;
    int h_ = l / WW, w_ = l % WW;
    int hs = (h_ + HH - SS) % HH, ws_ = (w_ + WW - SS) % WW;
    int bw = b * NWIN + (hs / WS) * 8 + (ws_ / WS);
    int n  = (hs % WS) * WS + (ws_ % WS);
    bf16* dst = xw + ((size_t)(bw * NW2 + n)) * C_;
    dst[lane]      = __float2bfloat16(d0 * inv * sc[lane]      + bi[lane]);
    dst[lane + 32] = __float2bfloat16(d1 * inv * sc[lane + 32] + bi[lane + 32]);
    dst[lane + 64] = __float2bfloat16(d2 * inv * sc[lane + 64] + bi[lane + 64]);
}

// ======== wide GEMM (N=288/384): 128 thr, BM=64, ACT 0/1 =====================
#define GST 40
#define BST 104
template<int ACT>
__global__ void __launch_bounds__(128) gemm_mma_kernel(
        const bf16* __restrict__ A, const bf16* __restrict__ W,
        const float* __restrict__ bias,
        bf16* __restrict__ outb, int M, int N, int K) {
    __shared__ bf16 As[64 * GST];
    __shared__ bf16 Bs[32 * BST];
    int tid = threadIdx.x;
    int w = tid >> 5, lane = tid & 31;
    int g = lane >> 2, t4 = lane & 3, l8 = lane & 7;
    int m0 = blockIdx.x * 64, n0 = blockIdx.y * 96;
    uint32_t as_u = smem_to_u32(As);
    uint32_t bs_u = smem_to_u32(Bs);

    float oc[12][4] = {};
    int alr = tid >> 1, alh = (tid & 1) * 16;
    const bf16* arow = A + (size_t)(m0 + alr) * K + alh;
    int brow = tid >> 2, bc0 = (tid & 3) * 8;
    const bf16* wrow = W + (size_t)brow * N + n0;

    uint4 apre0, apre1, bpre[3];
    {
        const uint4* ap = (const uint4*)arow;
        apre0 = ap[0]; apre1 = ap[1];
        #pragma unroll
        for (int j = 0; j < 3; j++)
            bpre[j] = *(const uint4*)(wrow + bc0 + j * 32);
    }
    const int NKT = K >> 5;
    for (int kt = 0; kt < NKT; kt++) {
        *(uint4*)&As[alr * GST + alh]     = apre0;
        *(uint4*)&As[alr * GST + alh + 8] = apre1;
        #pragma unroll
        for (int j = 0; j < 3; j++)
            *(uint4*)&Bs[brow * BST + bc0 + j * 32] = bpre[j];
        __syncthreads();
        if (kt + 1 < NKT) {
            int k0 = (kt + 1) * 32;
            const uint4* ap = (const uint4*)(arow + k0);
            apre0 = ap[0]; apre1 = ap[1];
            const bf16* wp = wrow + (size_t)k0 * N;
            #pragma unroll
            for (int j = 0; j < 3; j++)
                bpre[j] = *(const uint4*)(wp + bc0 + j * 32);
        }
        uint32_t af[2][4];
        #pragma unroll
        for (int kh = 0; kh < 2; kh++) {
            int r = 16 * w + l8 + ((lane >> 3) & 1) * 8;
            int c = 16 * kh + ((lane >> 4) & 1) * 8;
            ldsm4(af[kh], as_u + (uint32_t)(r * GST + c) * 2);
        }
        #pragma unroll
        for (int kh = 0; kh < 2; kh++) {
            uint32_t bfk[12][2];
            #pragma unroll
            for (int u = 0; u < 6; u++) {
                int r = 16 * kh + l8 + ((lane >> 3) & 1) * 8;
                int c = 16 * u + ((lane >> 4) & 1) * 8;
                uint32_t rr[4];
                ldsm4t(rr, bs_u + (uint32_t)(r * BST + c) * 2);
                bfk[2*u][0] = rr[0]; bfk[2*u][1] = rr[1];
                bfk[2*u+1][0] = rr[2]; bfk[2*u+1][1] = rr[3];
            }
            #pragma unroll
            for (int nj = 0; nj < 12; nj++)
                mma_bf16(oc[nj], af[kh], bfk[nj]);
        }
        if (kt + 1 < NKT) __syncthreads();
    }
    #pragma unroll
    for (int nj = 0; nj < 12; nj++) {
        int n = n0 + 8 * nj + 2 * t4;
        float2 bb = *(const float2*)(bias + n);
        #pragma unroll
        for (int half = 0; half < 2; half++) {
            int m = m0 + 16 * w + g + half * 8;
            float v0 = oc[nj][2*half]     + bb.x;
            float v1 = oc[nj][2*half + 1] + bb.y;
            if (ACT == 1) {
                float t0 = 0.7978845608028654f * (v0 + 0.044715f * v0 * v0 * v0);
                float t1 = 0.7978845608028654f * (v1 + 0.044715f * v1 * v1 * v1);
                v0 = 0.5f * v0 * (1.f + tanhf(t0));
                v1 = 0.5f * v1 * (1.f + tanhf(t1));
            }
            *(uint32_t*)(outb + (size_t)m * N + n) = cvt_bf16x2(v1, v0);
        }
    }
}

// ======== narrow pipelined GEMM (N=96, K=384): 64 thr, BM=32, fc2 ============
__global__ void __launch_bounds__(64) gemm32_mma_kernel(
        const bf16* __restrict__ A, const bf16* __restrict__ W,
        const float* __restrict__ bias, const float* __restrict__ add,
        float* __restrict__ outf, int K) {
    const int N = 96;
    __shared__ bf16 As[32 * GST];
    __shared__ bf16 Bs[32 * BST];
    int tid = threadIdx.x;
    int w = tid >> 5, lane = tid & 31;
    int g = lane >> 2, t4 = lane & 3, l8 = lane & 7;
    int m0 = blockIdx.x * 32;
    uint32_t as_u = smem_to_u32(As);
    uint32_t bs_u = smem_to_u32(Bs);

    float oc[12][4] = {};
    int alr = tid >> 1, alh = (tid & 1) * 16;
    const bf16* arow = A + (size_t)(m0 + alr) * K + alh;
    int brow = tid >> 1, bc0 = (tid & 1) * 48;
    const bf16* wrow = W + (size_t)brow * N + bc0;

    uint4 apre0, apre1, bpre[6];
    {
        const uint4* ap = (const uint4*)arow;
        apre0 = ap[0]; apre1 = ap[1];
        #pragma unroll
        for (int j = 0; j < 6; j++)
            bpre[j] = *(const uint4*)(wrow + j * 8);
    }
    const int NKT = K >> 5;
    for (int kt = 0; kt < NKT; kt++) {
        *(uint4*)&As[alr * GST + alh] = apre0;
        *(uint4*)&As[alr * GST + alh + 8] = apre1;
        #pragma unroll
        for (int j = 0; j < 6; j++)
            *(uint4*)&Bs[brow * BST + bc0 + j * 8] = bpre[j];
        __syncthreads();
        if (kt + 1 < NKT) {
            int k0 = (kt + 1) * 32;
            const uint4* ap = (const uint4*)(arow + k0);
            apre0 = ap[0]; apre1 = ap[1];
            const bf16* wp = wrow + (size_t)k0 * N;
            #pragma unroll
            for (int j = 0; j < 6; j++)
                bpre[j] = *(const uint4*)(wp + j * 8);
        }
        uint32_t af[2][4];
        #pragma unroll
        for (int kh = 0; kh < 2; kh++) {
            int r = 16 * w + l8 + ((lane >> 3) & 1) * 8;
            int c = 16 * kh + ((lane >> 4) & 1) * 8;
            ldsm4(af[kh], as_u + (uint32_t)(r * GST + c) * 2);
        }
        #pragma unroll
        for (int kh = 0; kh < 2; kh++) {
            uint32_t bfk[12][2];
            #pragma unroll
            for (int u = 0; u < 6; u++) {
                int r = 16 * kh + l8 + ((lane >> 3) & 1) * 8;
                int c = 16 * u + ((lane >> 4) & 1) * 8;
                uint32_t rr[4];
                ldsm4t(rr, bs_u + (uint32_t)(r * BST + c) * 2);
                bfk[2*u][0] = rr[0]; bfk[2*u][1] = rr[1];
                bfk[2*u+1][0] = rr[2]; bfk[2*u+1][1] = rr[3];
            }
            #pragma unroll
            for (int nj = 0; nj < 12; nj++)
                mma_bf16(oc[nj], af[kh], bfk[nj]);
        }
        if (kt + 1 < NKT) __syncthreads();
    }
    #pragma unroll
    for (int nj = 0; nj < 12; nj++) {
        int n = 8 * nj + 2 * t4;
        float2 bb = *(const float2*)(bias + n);
        #pragma unroll
        for (int half = 0; half < 2; half++) {
            int m = m0 + 16 * w + g + half * 8;
            float2 aa = *(const float2*)(add + (size_t)m * N + n);
            *(float2*)(outf + (size_t)m * N + n) =
                make_float2(oc[nj][2*half] + bb.x + aa.x,
                            oc[nj][2*half + 1] + bb.y + aa.y);
        }
    }
}

// ======== single-phase LN-GEMM (N=96, K=96): 64 thr, BM=32 ===================
// Loads full A(32x96) + B(96x96) + residual rows into smem up-front (one
// overlapped DRAM round), one barrier, 6 unrolled k-halves, smem epilogue.
// ACT: 2 = add[m] residual; 3 = add[t], t = inv-window-perm(m).
#define A96 104
template<int ACT>
__global__ void __launch_bounds__(64) gemm96_mma_kernel(
        const bf16* __restrict__ A, const bf16* __restrict__ W,
        const float* __restrict__ bias, const float* __restrict__ add,
        const float* __restrict__ ln_sc, const float* __restrict__ ln_bi,
        float* __restrict__ outf, bf16* __restrict__ outb) {
    const int N = 96, K = 96;
    __shared__ bf16  As[32 * A96];
    __shared__ bf16  Bs[96 * A96];
    __shared__ float Rs[32 * 96];
    __shared__ int   Ts[32];
    int tid = threadIdx.x;
    int w = tid >> 5, lane = tid & 31;
    int g = lane >> 2, t4 = lane & 3, l8 = lane & 7;
    int m0 = blockIdx.x * 32;
    uint32_t as_u = smem_to_u32(As);
    uint32_t bs_u = smem_to_u32(Bs);

    // ---- single load phase: A, B, resr (independent -> overlapped) ----
    {
        int ar = tid >> 1, ac = (tid & 1) * 48;       // A: row, 48-col half
        const uint4* ap = (const uint4*)(A + (size_t)(m0 + ar) * K + ac);
        #pragma unroll
        for (int j = 0; j < 6; j++)
            *(uint4*)&As[ar * A96 + ac + j * 8] = ap[j];
        #pragma unroll
        for (int j2 = 0; j2 < 3; j2++) {              // B: 3 half-rows/thread
            int hr = tid + j2 * 64;
            int br = hr >> 1, bc = (hr & 1) * 48;
            const uint4* bp = (const uint4*)(W + (size_t)br * N + bc);
            #pragma unroll
            for (int j = 0; j < 6; j++)
                *(uint4*)&Bs[br * A96 + bc + j * 8] = bp[j];
        }
        // residual rows (with permutation for ACT==3)
        int rr = tid >> 1, rc = (tid & 1) * 48;
        int m = m0 + rr;
        int t = m;
        if (ACT == 3) {
            int bw = m / NW2, n_ = m % NW2;
            int b = bw / NWIN, wi = bw % NWIN;
            int wh = wi >> 3, ww = wi & 7;
            int i = n_ / WS, j = n_ % WS;
            int hs = wh * WS + i, ws_ = ww * WS + j;
            int hh = (hs + SS) % HH, ww2 = (ws_ + SS) % WW;
            t = b * L_ + hh * WW + ww2;
        }
        if ((tid & 1) == 0) Ts[rr] = t;
        const uint4* rp = (const uint4*)(add + (size_t)t * C_ + rc);
        #pragma unroll
        for (int j = 0; j < 12; j++)
            *(uint4*)&Rs[rr * 96 + rc + j * 4] = rp[j];
    }
    __syncthreads();

    // ---- 6 unrolled k-halves ----
    float oc[12][4] = {};
    #pragma unroll
    for (int kh = 0; kh < 6; kh++) {
        uint32_t af[4];
        {
            int r = 16 * w + l8 + ((lane >> 3) & 1) * 8;
            int c = 16 * kh + ((lane >> 4) & 1) * 8;
            ldsm4(af, as_u + (uint32_t)(r * A96 + c) * 2);
        }
        uint32_t bfk[12][2];
        #pragma unroll
        for (int u = 0; u < 6; u++) {
            int r = 16 * kh + l8 + ((lane >> 3) & 1) * 8;
            int c = 16 * u + ((lane >> 4) & 1) * 8;
            uint32_t rr[4];
            ldsm4t(rr, bs_u + (uint32_t)(r * A96 + c) * 2);
            bfk[2*u][0] = rr[0]; bfk[2*u][1] = rr[1];
            bfk[2*u+1][0] = rr[2]; bfk[2*u+1][1] = rr[3];
        }
        #pragma unroll
        for (int nj = 0; nj < 12; nj++)
            mma_bf16(oc[nj], af, bfk[nj]);
    }

    // ---- fused residual + LN epilogue (resr from smem) ----
    #pragma unroll
    for (int half = 0; half < 2; half++) {
        int ml = 16 * w + g + half * 8;   // local row 0..31
        const float* resr = &Rs[ml * 96];
        float s = 0.f;
        #pragma unroll
        for (int nj = 0; nj < 12; nj++) {
            int n = 8 * nj + 2 * t4;
            float2 bb = *(const float2*)(bias + n);
            float v0 = oc[nj][2*half]     + bb.x + resr[n];
            float v1 = oc[nj][2*half + 1] + bb.y + resr[n + 1];
            oc[nj][2*half] = v0; oc[nj][2*half + 1] = v1;
            s += v0 + v1;
        }
        s += __shfl_xor_sync(0xffffffffu, s, 1);
        s += __shfl_xor_sync(0xffffffffu, s, 2);
        float mean = s * (1.0f / C_);
        float vs = 0.f;
        #pragma unroll
        for (int nj = 0; nj < 12; nj++) {
            float d0 = oc[nj][2*half]     - mean;
            float d1 = oc[nj][2*half + 1] - mean;
            vs += d0 * d0 + d1 * d1;
        }
        vs += __shfl_xor_sync(0xffffffffu, vs, 1);
        vs += __shfl_xor_sync(0xffffffffu, vs, 2);
        float inv = rsqrtf(vs * (1.0f / C_) + 1e-6f);
        int t = Ts[ml];
        float* xr = outf + (size_t)t * C_;
        bf16*  yr = outb + (size_t)t * C_;
        #pragma unroll
        for (int nj = 0; nj < 12; nj++) {
            int n = 8 * nj + 2 * t4;
            float v0 = oc[nj][2*half], v1 = oc[nj][2*half + 1];
            *(float2*)(xr + n) = make_float2(v0, v1);
            float2 ss = *(const float2*)(ln_sc + n);
            float2 bb2 = *(const float2*)(ln_bi + n);
            *(uint32_t*)(yr + n) = cvt_bf16x2((v1 - mean) * inv * ss.y + bb2.y,
                                              (v0 - mean) * inv * ss.x + bb2.x);
        }
    }
}

// ============ window attention via mma.sync (flash pattern, NKT=1) ===========
#define FST 40
__global__ void __launch_bounds__(128) win_attn_mma_kernel(const bf16* __restrict__ qkv,
                                                           bf16* __restrict__ out) {
    __shared__ bf16 Qs[64 * FST];
    __shared__ bf16 Ks[64 * FST];
    __shared__ bf16 Vs[64 * FST];
    __shared__ int  cntS[64];
    int tid = threadIdx.x;
    int w = tid >> 5, lane = tid & 31;
    int g = lane >> 2, t4 = lane & 3, l8 = lane & 7;
    int bw = blockIdx.x, h = blockIdx.y;
    const bf16* base = qkv + (size_t)bw * NW2 * C3 + h * HD;
    uint32_t qs_u = smem_to_u32(Qs);
    uint32_t ks_u = smem_to_u32(Ks);
    uint32_t vs_u = smem_to_u32(Vs);

    int lr = tid >> 1, lhf = (tid & 1) * 16;
    if (lr < NW2) {
        const uint4* qp = (const uint4*)(base + (size_t)lr * C3 + lhf);
        const uint4* kp = (const uint4*)(base + (size_t)lr * C3 + C_ + lhf);
        const uint4* vp = (const uint4*)(base + (size_t)lr * C3 + 2 * C_ + lhf);
        *(uint4*)&Qs[lr * FST + lhf]     = qp[0];
        *(uint4*)&Qs[lr * FST + lhf + 8] = qp[1];
        *(uint4*)&Ks[lr * FST + lhf]     = kp[0];
        *(uint4*)&Ks[lr * FST + lhf + 8] = kp[1];
        *(uint4*)&Vs[lr * FST + lhf]     = vp[0];
        *(uint4*)&Vs[lr * FST + lhf + 8] = vp[1];
    } else {
        uint4 z = make_uint4(0, 0, 0, 0);
        *(uint4*)&Qs[lr * FST + lhf]     = z;
        *(uint4*)&Qs[lr * FST + lhf + 8] = z;
        *(uint4*)&Ks[lr * FST + lhf]     = z;
        *(uint4*)&Ks[lr * FST + lhf + 8] = z;
        *(uint4*)&Vs[lr * FST + lhf]     = z;
        *(uint4*)&Vs[lr * FST + lhf + 8] = z;
    }
    if (tid < 64) {
        int cnt;
        if (tid < NW2) {
            int wi = bw % NWIN;
            int wh = wi >> 3, ww = wi & 7;
            int i = tid / WS, j = tid % WS;
            int hs = wh * WS + i, ws_ = ww * WS + j;
            int rh = (hs < HH - WS) ? 0 : ((hs < HH - SS) ? 1 : 2);
            int rw = (ws_ < WW - WS) ? 0 : ((ws_ < WW - SS) ? 1 : 2);
            cnt = rh * 3 + rw;
        } else {
            cnt = 9 + tid;
        }
        cntS[tid] = cnt;
    }
    __syncthreads();

    uint32_t qa[2][4];
    #pragma unroll
    for (int h2 = 0; h2 < 2; h2++) {
        int r = 16 * w + l8 + ((lane >> 3) & 1) * 8;
        int c = h2 * 16 + ((lane >> 4) & 1) * 8;
        ldsm4(qa[h2], qs_u + (uint32_t)(r * FST + c) * 2);
    }
    uint32_t kb[8][2][2];
    #pragma unroll
    for (int u = 0; u < 4; u++) {
        #pragma unroll
        for (int h2 = 0; h2 < 2; h2++) {
            int r = 16 * u + l8 + ((lane >> 4) & 1) * 8;
            int c = 16 * h2 + ((lane >> 3) & 1) * 8;
            uint32_t rr[4];
            ldsm4(rr, ks_u + (uint32_t)(r * FST + c) * 2);
            kb[2*u][h2][0] = rr[0]; kb[2*u][h2][1] = rr[1];
            kb[2*u+1][h2][0] = rr[2]; kb[2*u+1][h2][1] = rr[3];
        }
    }
    float sc_[8][4] = {};
    #pragma unroll
    for (int j = 0; j < 8; j++) {
        mma_bf16(sc_[j], qa[0], kb[j][0]);
        mma_bf16(sc_[j], qa[1], kb[j][1]);
    }
    int qA = 16 * w + g, qB = qA + 8;
    int cqA = cntS[qA], cqB = cntS[qB];
    const float scale = 0.17677669529663687f;
    ull EC2  = dup2(1.4426950408889634f);
    ull ENC2 = dup2(-1.4426950408889634f);
    float oc[4][4] = {};
    ull lpA = 0ULL, lpB = 0ULL;
    uint32_t pe[8][2];
    #pragma unroll
    for (int j = 0; j < 8; j++) {
        int k0 = 8 * j + 2 * t4;
        int ck0 = cntS[k0], ck1 = cntS[k0 + 1];
        float m00 = (ck0 == cqA) ? 0.f : -60.f;
        float m01 = (ck1 == cqA) ? 0.f : -60.f;
        float m10 = (ck0 == cqB) ? 0.f : -60.f;
        float m11 = (ck1 == cqB) ? 0.f : -60.f;
        ull e0 = fexp2pk_c(pack2(sc_[j][0] * scale + m00, sc_[j][1] * scale + m01), EC2, ENC2);
        lpA = fadd2(lpA, e0);
        float a0, a1; upk2(e0, a0, a1);
        pe[j][0] = cvt_bf16x2(a1, a0);
        ull e1 = fexp2pk_c(pack2(sc_[j][2] * scale + m10, sc_[j][3] * scale + m11), EC2, ENC2);
        lpB = fadd2(lpB, e1);
        float a2, a3; upk2(e1, a2, a3);
        pe[j][1] = cvt_bf16x2(a3, a2);
    }
    #pragma unroll
    for (int kk = 0; kk < 4; kk++) {
        uint32_t vb[4][2];
        #pragma unroll
        for (int u = 0; u < 2; u++) {
            int r = 16 * kk + l8 + ((lane >> 3) & 1) * 8;
            int c = 16 * u + ((lane >> 4) & 1) * 8;
            uint32_t rr[4];
            ldsm4t(rr, vs_u + (uint32_t)(r * FST + c) * 2);
            vb[2*u][0] = rr[0]; vb[2*u][1] = rr[1];
            vb[2*u+1][0] = rr[2]; vb[2*u+1][1] = rr[3];
        }
        uint32_t ap[4] = { pe[2*kk][0], pe[2*kk][1], pe[2*kk+1][0], pe[2*kk+1][1] };
        #pragma unroll
        for (int j = 0; j < 4; j++) mma_bf16(oc[j], ap, vb[j]);
    }
    float lAlo, lAhi, lBlo, lBhi;
    upk2(lpA, lAlo, lAhi);
    upk2(lpB, lBlo, lBhi);
    float lA = lAlo + lAhi, lB = lBlo + lBhi;
    lA += __shfl_xor_sync(0xffffffffu, lA, 1);
    lA += __shfl_xor_sync(0xffffffffu, lA, 2);
    lB += __shfl_xor_sync(0xffffffffu, lB, 1);
    lB += __shfl_xor_sync(0xffffffffu, lB, 2);
    float invA = 1.0f / lA, invB = 1.0f / lB;
    bf16* oA = out + (size_t)(bw * NW2 + qA) * C_ + h * HD + 2 * t4;
    bf16* oB = out + (size_t)(bw * NW2 + qB) * C_ + h * HD + 2 * t4;
    #pragma unroll
    for (int j = 0; j < 4; j++) {
        if (qA < NW2) *(uint32_t*)(oA + 8 * j) = cvt_bf16x2(oc[j][1] * invA, oc[j][0] * invA);
        if (qB < NW2) *(uint32_t*)(oB + 8 * j) = cvt_bf16x2(oc[j][3] * invB, oc[j][2] * invB);
    }
}

// ================= mma.sync bf16 flash attention (qtile 64) ==================
__global__ void __launch_bounds__(128) fa_mma_kernel(const bf16* __restrict__ qkv,
                                                     bf16* __restrict__ out) {
    __shared__ bf16 Qs[64 * FST];
    __shared__ bf16 Ks[2][64 * FST];
    __shared__ bf16 Vss[2][64 * FST];
    int tid = threadIdx.x;
    int w = tid >> 5, lane = tid & 31;
    int g = lane >> 2, t4 = lane & 3, l8 = lane & 7;
    int bh = blockIdx.x;
    int b = bh / NH, h = bh % NH;
    int q0 = blockIdx.y * 64;
    const bf16* base = qkv + (size_t)b * L_ * C3;
    uint32_t qs_u = smem_to_u32(Qs);
    uint32_t ks_u[2] = { smem_to_u32(Ks[0]), smem_to_u32(Ks[1]) };
    uint32_t vs_u[2] = { smem_to_u32(Vss[0]), smem_to_u32(Vss[1]) };

    int lr = tid >> 1, lhf = (tid & 1) * 16;
    {
        const uint4* qp = (const uint4*)(base + (size_t)(q0 + lr) * C3 + h * HD + lhf);
        *(uint4*)&Qs[lr * FST + lhf]     = qp[0];
        *(uint4*)&Qs[lr * FST + lhf + 8] = qp[1];
    }
    const bf16* kgp = base + C_     + h * HD + lhf;
    const bf16* vgp = base + 2 * C_ + h * HD + lhf;
    uint4 kr0, kr1, vr0, vr1;
    {
        const uint4* kp = (const uint4*)(kgp + (size_t)lr * C3);
        const uint4* vp = (const uint4*)(vgp + (size_t)lr * C3);
        kr0 = kp[0]; kr1 = kp[1]; vr0 = vp[0]; vr1 = vp[1];
    }
    *(uint4*)&Ks[0][lr * FST + lhf]      = kr0;
    *(uint4*)&Ks[0][lr * FST + lhf + 8]  = kr1;
    *(uint4*)&Vss[0][lr * FST + lhf]     = vr0;
    *(uint4*)&Vss[0][lr * FST + lhf + 8] = vr1;
    __syncthreads();

    uint32_t qa[2][4];
    #pragma unroll
    for (int h2 = 0; h2 < 2; h2++) {
        int r = 16 * w + l8 + ((lane >> 3) & 1) * 8;
        int c = h2 * 16 + ((lane >> 4) & 1) * 8;
        ldsm4(qa[h2], qs_u + (uint32_t)(r * FST + c) * 2);
    }

    float oc[4][4] = {};
    ull lpA = 0ULL, lpB = 0ULL;
    const float CSC = 0.17677669529663687f * 1.4426950408889634f;
    ull C2  = dup2(CSC);
    ull NC2 = dup2(-CSC);
    int p = 0;

    for (int kt = 0; kt < 49; kt++) {
        if (kt < 48) {
            size_t roff = (size_t)((kt + 1) * 64 + lr) * C3;
            const uint4* kp = (const uint4*)(kgp + roff);
            const uint4* vp = (const uint4*)(vgp + roff);
            kr0 = kp[0]; kr1 = kp[1]; vr0 = vp[0]; vr1 = vp[1];
        }
        uint32_t kb[8][2][2];
        #pragma unroll
        for (int u = 0; u < 4; u++) {
            #pragma unroll
            for (int h2 = 0; h2 < 2; h2++) {
                int r = 16 * u + l8 + ((lane >> 4) & 1) * 8;
                int c = 16 * h2 + ((lane >> 3) & 1) * 8;
                uint32_t rr[4];
                ldsm4(rr, ks_u[p] + (uint32_t)(r * FST + c) * 2);
                kb[2*u][h2][0] = rr[0]; kb[2*u][h2][1] = rr[1];
                kb[2*u+1][h2][0] = rr[2]; kb[2*u+1][h2][1] = rr[3];
            }
        }
        float sc_[8][4] = {};
        #pragma unroll
        for (int j = 0; j < 8; j++) {
            mma_bf16(sc_[j], qa[0], kb[j][0]);
            mma_bf16(sc_[j], qa[1], kb[j][1]);
        }
        uint32_t pe[8][2];
        #pragma unroll
        for (int j = 0; j < 8; j++) {
            ull e0 = fexp2pk_c(pack2(sc_[j][0], sc_[j][1]), C2, NC2);
            lpA = fadd2(lpA, e0);
            float a0, a1; upk2(e0, a0, a1);
            pe[j][0] = cvt_bf16x2(a1, a0);
            ull e1 = fexp2pk_c(pack2(sc_[j][2], sc_[j][3]), C2, NC2);
            lpB = fadd2(lpB, e1);
            float a2, a3; upk2(e1, a2, a3);
            pe[j][1] = cvt_bf16x2(a3, a2);
        }
        #pragma unroll
        for (int kk = 0; kk < 4; kk++) {
            uint32_t vb[4][2];
            #pragma unroll
            for (int u = 0; u < 2; u++) {
                int r = 16 * kk + l8 + ((lane >> 3) & 1) * 8;
                int c = 16 * u + ((lane >> 4) & 1) * 8;
                uint32_t rr[4];
                ldsm4t(rr, vs_u[p] + (uint32_t)(r * FST + c) * 2);
                vb[2*u][0] = rr[0]; vb[2*u][1] = rr[1];
                vb[2*u+1][0] = rr[2]; vb[2*u+1][1] = rr[3];
            }
            uint32_t ap[4] = { pe[2*kk][0], pe[2*kk][1], pe[2*kk+1][0], pe[2*kk+1][1] };
            #pragma unroll
            for (int j = 0; j < 4; j++) mma_bf16(oc[j], ap, vb[j]);
        }
        if (kt < 48) {
            int q = p ^ 1;
            *(uint4*)&Ks[q][lr * FST + lhf]      = kr0;
            *(uint4*)&Ks[q][lr * FST + lhf + 8]  = kr1;
            *(uint4*)&Vss[q][lr * FST + lhf]     = vr0;
            *(uint4*)&Vss[q][lr * FST + lhf + 8] = vr1;
            __syncthreads();
            p = q;
        }
    }
    float lAlo, lAhi, lBlo, lBhi;
    upk2(lpA, lAlo, lAhi);
    upk2(lpB, lBlo, lBhi);
    float lA = lAlo + lAhi, lB = lBlo + lBhi;
    lA += __shfl_xor_sync(0xffffffffu, lA, 1);
    lA += __shfl_xor_sync(0xffffffffu, lA, 2);
    lB += __shfl_xor_sync(0xffffffffu, lB, 1);
    lB += __shfl_xor_sync(0xffffffffu, lB, 2);
    float invA = 1.0f / lA, invB = 1.0f / lB;
    int qrA = q0 + 16 * w + g;
    bf16* oA = out + (size_t)(b * L_ + qrA) * C_ + h * HD + 2 * t4;
    bf16* oB = oA + 8 * C_;
    #pragma unroll
    for (int j = 0; j < 4; j++) {
        *(uint32_t*)(oA + 8 * j) = cvt_bf16x2(oc[j][1] * invA, oc[j][0] * invA);
        *(uint32_t*)(oB + 8 * j) = cvt_bf16x2(oc[j][3] * invB, oc[j][2] * invB);
    }
}

// ---------------- launcher ----------------
extern "C" void kernel_launch(void* const* d_in, const int* in_sizes, int n_in,
                              void* d_out, int out_size) {
    const float* x        = (const float*)d_in[0];
    const float* n1_s     = (const float*)d_in[3];
    const float* n1_b     = (const float*)d_in[4];
    const float* qkv_w    = (const float*)d_in[5];
    const float* qkv_b    = (const float*)d_in[6];
    const float* proj_w   = (const float*)d_in[7];
    const float* proj_b   = (const float*)d_in[8];
    const float* ln1_s    = (const float*)d_in[9];
    const float* ln1_b    = (const float*)d_in[10];
    const float* qkv2_w   = (const float*)d_in[11];
    const float* qkv2_b   = (const float*)d_in[12];
    const float* out_w    = (const float*)d_in[13];
    const float* out_b    = (const float*)d_in[14];
    const float* ln2_s    = (const float*)d_in[15];
    const float* ln2_b    = (const float*)d_in[16];
    const float* fc1_w    = (const float*)d_in[17];
    const float* fc1_b    = (const float*)d_in[18];
    const float* fc2_w    = (const float*)d_in[19];
    const float* fc2_b    = (const float*)d_in[20];
    float* out = (float*)d_out;

    bf16 *xw, *qkvw, *attnw, *y, *qkv2, *ao, *h1, *wbf;
    float *x1, *x2;
    cudaGetSymbolAddress((void**)&xw,    g_xw);
    cudaGetSymbolAddress((void**)&qkvw,  g_qkvw);
    cudaGetSymbolAddress((void**)&attnw, g_attnw);
    cudaGetSymbolAddress((void**)&x1,    g_x1);
    cudaGetSymbolAddress((void**)&y,     g_y);
    cudaGetSymbolAddress((void**)&qkv2,  g_qkv2);
    cudaGetSymbolAddress((void**)&ao,    g_ao);
    cudaGetSymbolAddress((void**)&x2,    g_x2);
    cudaGetSymbolAddress((void**)&h1,    g_h1);
    cudaGetSymbolAddress((void**)&wbf,   g_wbf);

    const int MB  = NTOK / 64;   // 196
    const int MB2 = NTOK / 32;   // 392

    ln1_wconv_kernel<<<LN1_BLOCKS + 576, 256>>>(x, n1_s, n1_b, xw,
                                                qkv_w, proj_w, qkv2_w, out_w, fc1_w, fc2_w, wbf,
                                                out, out_size);
    gemm_mma_kernel<0><<<dim3(MB, 3), 128>>>(xw, wbf + W_QKV, qkv_b, qkvw, NTOK, C3, C_);
    win_attn_mma_kernel<<<dim3(BW, NH), 128>>>(qkvw, attnw);
    gemm96_mma_kernel<3><<<MB2, 64>>>(attnw, wbf + W_PROJ, proj_b, x, ln1_s, ln1_b, x1, y);
    gemm_mma_kernel<0><<<dim3(MB, 3), 128>>>(y, wbf + W_QKV2, qkv2_b, qkv2, NTOK, C3, C_);
    fa_mma_kernel<<<dim3(B_ * NH, L_ / 64), 128>>>(qkv2, ao);
    gemm96_mma_kernel<2><<<MB2, 64>>>(ao, wbf + W_OUT, out_b, x1, ln2_s, ln2_b, x2, y);
    gemm_mma_kernel<1><<<dim3(MB, 4), 128>>>(y, wbf + W_FC1, fc1_b, h1, NTOK, C4, C_);
    gemm32_mma_kernel<<<MB2, 64>>>(h1, wbf + W_FC2, fc2_b, x2, out, C4);
}

// round 17
// speedup vs baseline: 1.0263x; 1.0263x over previous
#include <cuda_runtime.h>
#include <cuda_bf16.h>
#include <cstdint>

// ---------------- problem constants (fixed shapes) ----------------
#define B_   4
#define HH   56
#define WW   56
#define C_   96
#define L_   (HH*WW)          // 3136
#define NH   3
#define HD   32
#define WS   7
#define SS   3
#define NWIN 64
#define BW   (B_*NWIN)        // 256
#define NW2  (WS*WS)          // 49
#define NTOK (B_*L_)          // 12544
#define C3   (3*C_)           // 288
#define C4   (4*C_)           // 384

typedef unsigned long long ull;
typedef __nv_bfloat16 bf16;

// ---------------- scratch (device globals; zero-init, no runtime alloc) ------
__device__ bf16  g_xw   [NTOK*C_];
__device__ bf16  g_qkvw [NTOK*C3];
__device__ bf16  g_attnw[NTOK*C_];
__device__ float g_x1   [NTOK*C_];
__device__ bf16  g_y    [NTOK*C_];
__device__ bf16  g_qkv2 [NTOK*C3];
__device__ bf16  g_ao   [NTOK*C_];
__device__ float g_x2   [NTOK*C_];
__device__ bf16  g_h1   [NTOK*C4];
__device__ bf16  g_wbf  [147456];     // all six weight matrices, bf16

// weight arena offsets
#define W_QKV  0
#define W_PROJ 27648
#define W_QKV2 36864
#define W_OUT  64512
#define W_FC1  73728
#define W_FC2  110592

// ---------------- packed f32x2 helpers ----------------
__device__ __forceinline__ ull ffma2(ull a, ull b, ull c) {
    ull d; asm("fma.rn.f32x2 %0,%1,%2,%3;" : "=l"(d) : "l"(a), "l"(b), "l"(c)); return d;
}
__device__ __forceinline__ ull fadd2(ull a, ull b) {
    ull d; asm("add.rn.f32x2 %0,%1,%2;" : "=l"(d) : "l"(a), "l"(b)); return d;
}
__device__ __forceinline__ ull fmul2(ull a, ull b) {
    ull d; asm("mul.rn.f32x2 %0,%1,%2;" : "=l"(d) : "l"(a), "l"(b)); return d;
}
__device__ __forceinline__ ull dup2(float a) {
    ull r; asm("mov.b64 %0,{%1,%1};" : "=l"(r) : "f"(a)); return r;
}
__device__ __forceinline__ void upk2(ull x, float& a, float& b) {
    asm("mov.b64 {%0,%1},%2;" : "=f"(a), "=f"(b) : "l"(x));
}
__device__ __forceinline__ ull pack2(float lo, float hi) {
    ull r; asm("mov.b64 %0,{%1,%2};" : "=l"(r) : "f"(lo), "f"(hi)); return r;
}
#define ULL2(x) ((((ull)(x)) << 32) | (ull)(x))

// packed exp with FOLDED scale: returns exp(s * K) where C2 = dup2(K*log2e),
// NC2 = dup2(-K*log2e). Negated-f formulation, 4-term poly (rel err <= 4.2e-5).
__device__ __forceinline__ ull fexp2pk_c(ull s2, ull C2, ull NC2) {
    const ull MAG  = ULL2(0x4B400000u);
    const ull NMAG = ULL2(0xCB400000u);
    ull y2 = ffma2(s2, C2, MAG);
    ull r2 = fadd2(y2, NMAG);
    ull f2 = ffma2(s2, NC2, r2);
    ull p2 = ffma2(dup2(0.0096181292f), f2, dup2(-0.0555041087f));
    p2 = ffma2(p2, f2, dup2(0.2402265070f));
    p2 = ffma2(p2, f2, dup2(-0.6931471806f));
    p2 = ffma2(p2, f2, dup2(1.0f));
    unsigned ylo = (unsigned)y2, yhi = (unsigned)(y2 >> 32);
    unsigned slo = (ylo + 0xB4C0007Fu) << 23;
    unsigned shi = (yhi + 0xB4C0007Fu) << 23;
    return fmul2(p2, ((ull)shi << 32) | (ull)slo);
}

__device__ __forceinline__ float wred(float v) {
    #pragma unroll
    for (int o = 16; o > 0; o >>= 1) v += __shfl_xor_sync(0xffffffffu, v, o);
    return v;
}

// ---------------- mma.sync / ldmatrix primitives ----------------
__device__ __forceinline__ uint32_t smem_to_u32(const void* p) {
    uint32_t a;
    asm("{ .reg .u64 t; cvta.to.shared.u64 t, %1; cvt.u32.u64 %0, t; }" : "=r"(a) : "l"(p));
    return a;
}
__device__ __forceinline__ uint32_t cvt_bf16x2(float hi, float lo) {
    uint32_t r; asm("cvt.rn.bf16x2.f32 %0, %1, %2;" : "=r"(r) : "f"(hi), "f"(lo)); return r;
}
__device__ __forceinline__ void mma_bf16(float* c, const uint32_t* a, const uint32_t* b) {
    asm volatile("mma.sync.aligned.m16n8k16.row.col.f32.bf16.bf16.f32 "
        "{%0,%1,%2,%3},{%4,%5,%6,%7},{%8,%9},{%0,%1,%2,%3};"
        : "+f"(c[0]), "+f"(c[1]), "+f"(c[2]), "+f"(c[3])
        : "r"(a[0]), "r"(a[1]), "r"(a[2]), "r"(a[3]), "r"(b[0]), "r"(b[1]));
}
__device__ __forceinline__ void ldsm4(uint32_t* r, uint32_t addr) {
    asm volatile("ldmatrix.sync.aligned.m8n8.x4.shared.b16 {%0,%1,%2,%3},[%4];"
        : "=r"(r[0]), "=r"(r[1]), "=r"(r[2]), "=r"(r[3]) : "r"(addr));
}
__device__ __forceinline__ void ldsm4t(uint32_t* r, uint32_t addr) {
    asm volatile("ldmatrix.sync.aligned.m8n8.x4.trans.shared.b16 {%0,%1,%2,%3},[%4];"
        : "=r"(r[0]), "=r"(r[1]), "=r"(r[2]), "=r"(r[3]) : "r"(addr));
}

// ------- combined: LN1+shift+window partition (blocks 0..1567) ---------------
// -------           weight fp32->bf16 conversion + tail (blocks >= 1568) ------
#define LN1_BLOCKS (NTOK / 8)
__global__ void ln1_wconv_kernel(const float* __restrict__ x,
                                 const float* __restrict__ sc,
                                 const float* __restrict__ bi,
                                 bf16* __restrict__ xw,
                                 const float* __restrict__ a0, const float* __restrict__ a1,
                                 const float* __restrict__ a2, const float* __restrict__ a3,
                                 const float* __restrict__ a4, const float* __restrict__ a5,
                                 bf16* __restrict__ wdst,
                                 float* __restrict__ out, int out_size) {
    if (blockIdx.x >= LN1_BLOCKS) {
        if (blockIdx.x == LN1_BLOCKS) {
            int ti = NTOK * C_ + (int)threadIdx.x;
            if (ti < out_size) out[ti] = 56.0f;
        }
        int i = (blockIdx.x - LN1_BLOCKS) * 256 + threadIdx.x;
        if (i >= 147456) return;
        const float* src; int off;
        if      (i < W_PROJ) { src = a0; off = W_QKV;  }
        else if (i < W_QKV2) { src = a1; off = W_PROJ; }
        else if (i < W_OUT)  { src = a2; off = W_QKV2; }
        else if (i < W_FC1)  { src = a3; off = W_OUT;  }
        else if (i < W_FC2)  { src = a4; off = W_FC1;  }
        else                 { src = a5; off = W_FC2;  }
        wdst[i] = __float2bfloat16(src[i - off]);
        return;
    }
    int warp = (blockIdx.x * blockDim.x + threadIdx.x) >> 5;
    int lane = threadIdx.x & 31;
    const float* row = x + (size_t)warp * C_;
    float v0 = row[lane], v1 = row[lane + 32], v2 = row[lane + 64];
    float mean = wred(v0 + v1 + v2) * (1.0f / C_);
    float d0 = v0 - mean, d1 = v1 - mean, d2 = v2 - mean;
    float var = wred(d0*d0 + d1*d1 + d2*d2) * (1.0f / C_);
    float inv = rsqrtf(var + 1e-6f);
    int b = warp / L_, l = warp % L_;
    int h_ = l / WW, w_ = l % WW;
    int hs = (h_ + HH - SS) % HH, ws_ = (w_ + WW - SS) % WW;
    int bw = b * NWIN + (hs / WS) * 8 + (ws_ / WS);
    int n  = (hs % WS) * WS + (ws_ % WS);
    bf16* dst = xw + ((size_t)(bw * NW2 + n)) * C_;
    dst[lane]      = __float2bfloat16(d0 * inv * sc[lane]      + bi[lane]);
    dst[lane + 32] = __float2bfloat16(d1 * inv * sc[lane + 32] + bi[lane + 32]);
    dst[lane + 64] = __float2bfloat16(d2 * inv * sc[lane + 64] + bi[lane + 64]);
}

// ======== wide GEMM (N=288/384): 128 thr, BM=64, ACT 0/1 =====================
#define GST 40
#define BST 104
template<int ACT>
__global__ void __launch_bounds__(128) gemm_mma_kernel(
        const bf16* __restrict__ A, const bf16* __restrict__ W,
        const float* __restrict__ bias,
        bf16* __restrict__ outb, int M, int N, int K) {
    __shared__ bf16 As[64 * GST];
    __shared__ bf16 Bs[32 * BST];
    int tid = threadIdx.x;
    int w = tid >> 5, lane = tid & 31;
    int g = lane >> 2, t4 = lane & 3, l8 = lane & 7;
    int m0 = blockIdx.x * 64, n0 = blockIdx.y * 96;
    uint32_t as_u = smem_to_u32(As);
    uint32_t bs_u = smem_to_u32(Bs);

    float oc[12][4] = {};
    int alr = tid >> 1, alh = (tid & 1) * 16;
    const bf16* arow = A + (size_t)(m0 + alr) * K + alh;
    int brow = tid >> 2, bc0 = (tid & 3) * 8;
    const bf16* wrow = W + (size_t)brow * N + n0;

    uint4 apre0, apre1, bpre[3];
    {
        const uint4* ap = (const uint4*)arow;
        apre0 = ap[0]; apre1 = ap[1];
        #pragma unroll
        for (int j = 0; j < 3; j++)
            bpre[j] = *(const uint4*)(wrow + bc0 + j * 32);
    }
    const int NKT = K >> 5;
    for (int kt = 0; kt < NKT; kt++) {
        *(uint4*)&As[alr * GST + alh]     = apre0;
        *(uint4*)&As[alr * GST + alh + 8] = apre1;
        #pragma unroll
        for (int j = 0; j < 3; j++)
            *(uint4*)&Bs[brow * BST + bc0 + j * 32] = bpre[j];
        __syncthreads();
        if (kt + 1 < NKT) {
            int k0 = (kt + 1) * 32;
            const uint4* ap = (const uint4*)(arow + k0);
            apre0 = ap[0]; apre1 = ap[1];
            const bf16* wp = wrow + (size_t)k0 * N;
            #pragma unroll
            for (int j = 0; j < 3; j++)
                bpre[j] = *(const uint4*)(wp + bc0 + j * 32);
        }
        uint32_t af[2][4];
        #pragma unroll
        for (int kh = 0; kh < 2; kh++) {
            int r = 16 * w + l8 + ((lane >> 3) & 1) * 8;
            int c = 16 * kh + ((lane >> 4) & 1) * 8;
            ldsm4(af[kh], as_u + (uint32_t)(r * GST + c) * 2);
        }
        #pragma unroll
        for (int kh = 0; kh < 2; kh++) {
            uint32_t bfk[12][2];
            #pragma unroll
            for (int u = 0; u < 6; u++) {
                int r = 16 * kh + l8 + ((lane >> 3) & 1) * 8;
                int c = 16 * u + ((lane >> 4) & 1) * 8;
                uint32_t rr[4];
                ldsm4t(rr, bs_u + (uint32_t)(r * BST + c) * 2);
                bfk[2*u][0] = rr[0]; bfk[2*u][1] = rr[1];
                bfk[2*u+1][0] = rr[2]; bfk[2*u+1][1] = rr[3];
            }
            #pragma unroll
            for (int nj = 0; nj < 12; nj++)
                mma_bf16(oc[nj], af[kh], bfk[nj]);
        }
        if (kt + 1 < NKT) __syncthreads();
    }
    #pragma unroll
    for (int nj = 0; nj < 12; nj++) {
        int n = n0 + 8 * nj + 2 * t4;
        float2 bb = *(const float2*)(bias + n);
        #pragma unroll
        for (int half = 0; half < 2; half++) {
            int m = m0 + 16 * w + g + half * 8;
            float v0 = oc[nj][2*half]     + bb.x;
            float v1 = oc[nj][2*half + 1] + bb.y;
            if (ACT == 1) {
                float t0 = 0.7978845608028654f * (v0 + 0.044715f * v0 * v0 * v0);
                float t1 = 0.7978845608028654f * (v1 + 0.044715f * v1 * v1 * v1);
                v0 = 0.5f * v0 * (1.f + tanhf(t0));
                v1 = 0.5f * v1 * (1.f + tanhf(t1));
            }
            *(uint32_t*)(outb + (size_t)m * N + n) = cvt_bf16x2(v1, v0);
        }
    }
}

// ======== narrow GEMM (N=96): 64 thr, BM=32, 392 blocks (R15 version) ========
// ACT: 0 = bias + add residual -> outf (fc2 -> out)
//      2 = bias + add[m] residual -> outf[m]=v, outb[m]=LN(v)
//      3 = bias + add[t] residual, t = inv-window-perm(m) -> outf[t], outb[t]=LN(v)
template<int ACT>
__global__ void __launch_bounds__(64) gemm32_mma_kernel(
        const bf16* __restrict__ A, const bf16* __restrict__ W,
        const float* __restrict__ bias, const float* __restrict__ add,
        const float* __restrict__ ln_sc, const float* __restrict__ ln_bi,
        float* __restrict__ outf, bf16* __restrict__ outb, int K) {
    const int N = 96;
    __shared__ bf16 As[32 * GST];
    __shared__ bf16 Bs[32 * BST];
    int tid = threadIdx.x;
    int w = tid >> 5, lane = tid & 31;
    int g = lane >> 2, t4 = lane & 3, l8 = lane & 7;
    int m0 = blockIdx.x * 32;
    uint32_t as_u = smem_to_u32(As);
    uint32_t bs_u = smem_to_u32(Bs);

    float oc[12][4] = {};
    int alr = tid >> 1, alh = (tid & 1) * 16;
    const bf16* arow = A + (size_t)(m0 + alr) * K + alh;
    int brow = tid >> 1, bc0 = (tid & 1) * 48;
    const bf16* wrow = W + (size_t)brow * N + bc0;

    uint4 apre0, apre1, bpre[6];
    {
        const uint4* ap = (const uint4*)arow;
        apre0 = ap[0]; apre1 = ap[1];
        #pragma unroll
        for (int j = 0; j < 6; j++)
            bpre[j] = *(const uint4*)(wrow + j * 8);
    }
    const int NKT = K >> 5;
    for (int kt = 0; kt < NKT; kt++) {
        *(uint4*)&As[alr * GST + alh] = apre0;
        *(uint4*)&As[alr * GST + alh + 8] = apre1;
        #pragma unroll
        for (int j = 0; j < 6; j++)
            *(uint4*)&Bs[brow * BST + bc0 + j * 8] = bpre[j];
        __syncthreads();
        if (kt + 1 < NKT) {
            int k0 = (kt + 1) * 32;
            const uint4* ap = (const uint4*)(arow + k0);
            apre0 = ap[0]; apre1 = ap[1];
            const bf16* wp = wrow + (size_t)k0 * N;
            #pragma unroll
            for (int j = 0; j < 6; j++)
                bpre[j] = *(const uint4*)(wp + j * 8);
        }
        uint32_t af[2][4];
        #pragma unroll
        for (int kh = 0; kh < 2; kh++) {
            int r = 16 * w + l8 + ((lane >> 3) & 1) * 8;
            int c = 16 * kh + ((lane >> 4) & 1) * 8;
            ldsm4(af[kh], as_u + (uint32_t)(r * GST + c) * 2);
        }
        #pragma unroll
        for (int kh = 0; kh < 2; kh++) {
            uint32_t bfk[12][2];
            #pragma unroll
            for (int u = 0; u < 6; u++) {
                int r = 16 * kh + l8 + ((lane >> 3) & 1) * 8;
                int c = 16 * u + ((lane >> 4) & 1) * 8;
                uint32_t rr[4];
                ldsm4t(rr, bs_u + (uint32_t)(r * BST + c) * 2);
                bfk[2*u][0] = rr[0]; bfk[2*u][1] = rr[1];
                bfk[2*u+1][0] = rr[2]; bfk[2*u+1][1] = rr[3];
            }
            #pragma unroll
            for (int nj = 0; nj < 12; nj++)
                mma_bf16(oc[nj], af[kh], bfk[nj]);
        }
        if (kt + 1 < NKT) __syncthreads();
    }
    if (ACT == 0) {
        #pragma unroll
        for (int nj = 0; nj < 12; nj++) {
            int n = 8 * nj + 2 * t4;
            float2 bb = *(const float2*)(bias + n);
            #pragma unroll
            for (int half = 0; half < 2; half++) {
                int m = m0 + 16 * w + g + half * 8;
                float2 aa = *(const float2*)(add + (size_t)m * N + n);
                *(float2*)(outf + (size_t)m * N + n) =
                    make_float2(oc[nj][2*half] + bb.x + aa.x,
                                oc[nj][2*half + 1] + bb.y + aa.y);
            }
        }
    } else {
        #pragma unroll
        for (int half = 0; half < 2; half++) {
            int m = m0 + 16 * w + g + half * 8;
            int t = m;
            if (ACT == 3) {
                int bw = m / NW2, n_ = m % NW2;
                int b = bw / NWIN, wi = bw % NWIN;
                int wh = wi >> 3, ww = wi & 7;
                int i = n_ / WS, j = n_ % WS;
                int hs = wh * WS + i, ws_ = ww * WS + j;
                int hh = (hs + SS) % HH, ww2 = (ws_ + SS) % WW;
                t = b * L_ + hh * WW + ww2;
            }
            const float* resr = add + (size_t)t * C_;
            float s = 0.f;
            #pragma unroll
            for (int nj = 0; nj < 12; nj++) {
                int n = 8 * nj + 2 * t4;
                float2 bb = *(const float2*)(bias + n);
                float2 rr = *(const float2*)(resr + n);
                float v0 = oc[nj][2*half]     + bb.x + rr.x;
                float v1 = oc[nj][2*half + 1] + bb.y + rr.y;
                oc[nj][2*half] = v0; oc[nj][2*half + 1] = v1;
                s += v0 + v1;
            }
            s += __shfl_xor_sync(0xffffffffu, s, 1);
            s += __shfl_xor_sync(0xffffffffu, s, 2);
            float mean = s * (1.0f / C_);
            float vs = 0.f;
            #pragma unroll
            for (int nj = 0; nj < 12; nj++) {
                float d0 = oc[nj][2*half]     - mean;
                float d1 = oc[nj][2*half + 1] - mean;
                vs += d0 * d0 + d1 * d1;
            }
            vs += __shfl_xor_sync(0xffffffffu, vs, 1);
            vs += __shfl_xor_sync(0xffffffffu, vs, 2);
            float inv = rsqrtf(vs * (1.0f / C_) + 1e-6f);
            float* xr = outf + (size_t)t * C_;
            bf16*  yr = outb + (size_t)t * C_;
            #pragma unroll
            for (int nj = 0; nj < 12; nj++) {
                int n = 8 * nj + 2 * t4;
                float v0 = oc[nj][2*half], v1 = oc[nj][2*half + 1];
                *(float2*)(xr + n) = make_float2(v0, v1);
                float2 ss = *(const float2*)(ln_sc + n);
                float2 bb2 = *(const float2*)(ln_bi + n);
                *(uint32_t*)(yr + n) = cvt_bf16x2((v1 - mean) * inv * ss.y + bb2.y,
                                                  (v0 - mean) * inv * ss.x + bb2.x);
            }
        }
    }
}

// ============ window attention via mma.sync (flash pattern, NKT=1) ===========
#define FST 40
__global__ void __launch_bounds__(128) win_attn_mma_kernel(const bf16* __restrict__ qkv,
                                                           bf16* __restrict__ out) {
    __shared__ bf16 Qs[64 * FST];
    __shared__ bf16 Ks[64 * FST];
    __shared__ bf16 Vs[64 * FST];
    __shared__ int  cntS[64];
    int tid = threadIdx.x;
    int w = tid >> 5, lane = tid & 31;
    int g = lane >> 2, t4 = lane & 3, l8 = lane & 7;
    int bw = blockIdx.x, h = blockIdx.y;
    const bf16* base = qkv + (size_t)bw * NW2 * C3 + h * HD;
    uint32_t qs_u = smem_to_u32(Qs);
    uint32_t ks_u = smem_to_u32(Ks);
    uint32_t vs_u = smem_to_u32(Vs);

    int lr = tid >> 1, lhf = (tid & 1) * 16;
    if (lr < NW2) {
        const uint4* qp = (const uint4*)(base + (size_t)lr * C3 + lhf);
        const uint4* kp = (const uint4*)(base + (size_t)lr * C3 + C_ + lhf);
        const uint4* vp = (const uint4*)(base + (size_t)lr * C3 + 2 * C_ + lhf);
        *(uint4*)&Qs[lr * FST + lhf]     = qp[0];
        *(uint4*)&Qs[lr * FST + lhf + 8] = qp[1];
        *(uint4*)&Ks[lr * FST + lhf]     = kp[0];
        *(uint4*)&Ks[lr * FST + lhf + 8] = kp[1];
        *(uint4*)&Vs[lr * FST + lhf]     = vp[0];
        *(uint4*)&Vs[lr * FST + lhf + 8] = vp[1];
    } else {
        uint4 z = make_uint4(0, 0, 0, 0);
        *(uint4*)&Qs[lr * FST + lhf]     = z;
        *(uint4*)&Qs[lr * FST + lhf + 8] = z;
        *(uint4*)&Ks[lr * FST + lhf]     = z;
        *(uint4*)&Ks[lr * FST + lhf + 8] = z;
        *(uint4*)&Vs[lr * FST + lhf]     = z;
        *(uint4*)&Vs[lr * FST + lhf + 8] = z;
    }
    if (tid < 64) {
        int cnt;
        if (tid < NW2) {
            int wi = bw % NWIN;
            int wh = wi >> 3, ww = wi & 7;
            int i = tid / WS, j = tid % WS;
            int hs = wh * WS + i, ws_ = ww * WS + j;
            int rh = (hs < HH - WS) ? 0 : ((hs < HH - SS) ? 1 : 2);
            int rw = (ws_ < WW - WS) ? 0 : ((ws_ < WW - SS) ? 1 : 2);
            cnt = rh * 3 + rw;
        } else {
            cnt = 9 + tid;
        }
        cntS[tid] = cnt;
    }
    __syncthreads();

    uint32_t qa[2][4];
    #pragma unroll
    for (int h2 = 0; h2 < 2; h2++) {
        int r = 16 * w + l8 + ((lane >> 3) & 1) * 8;
        int c = h2 * 16 + ((lane >> 4) & 1) * 8;
        ldsm4(qa[h2], qs_u + (uint32_t)(r * FST + c) * 2);
    }
    uint32_t kb[8][2][2];
    #pragma unroll
    for (int u = 0; u < 4; u++) {
        #pragma unroll
        for (int h2 = 0; h2 < 2; h2++) {
            int r = 16 * u + l8 + ((lane >> 4) & 1) * 8;
            int c = 16 * h2 + ((lane >> 3) & 1) * 8;
            uint32_t rr[4];
            ldsm4(rr, ks_u + (uint32_t)(r * FST + c) * 2);
            kb[2*u][h2][0] = rr[0]; kb[2*u][h2][1] = rr[1];
            kb[2*u+1][h2][0] = rr[2]; kb[2*u+1][h2][1] = rr[3];
        }
    }
    float sc_[8][4] = {};
    #pragma unroll
    for (int j = 0; j < 8; j++) {
        mma_bf16(sc_[j], qa[0], kb[j][0]);
        mma_bf16(sc_[j], qa[1], kb[j][1]);
    }
    int qA = 16 * w + g, qB = qA + 8;
    int cqA = cntS[qA], cqB = cntS[qB];
    const float scale = 0.17677669529663687f;
    ull EC2  = dup2(1.4426950408889634f);
    ull ENC2 = dup2(-1.4426950408889634f);
    float oc[4][4] = {};
    ull lpA = 0ULL, lpB = 0ULL;
    uint32_t pe[8][2];
    #pragma unroll
    for (int j = 0; j < 8; j++) {
        int k0 = 8 * j + 2 * t4;
        int ck0 = cntS[k0], ck1 = cntS[k0 + 1];
        float m00 = (ck0 == cqA) ? 0.f : -60.f;
        float m01 = (ck1 == cqA) ? 0.f : -60.f;
        float m10 = (ck0 == cqB) ? 0.f : -60.f;
        float m11 = (ck1 == cqB) ? 0.f : -60.f;
        ull e0 = fexp2pk_c(pack2(sc_[j][0] * scale + m00, sc_[j][1] * scale + m01), EC2, ENC2);
        lpA = fadd2(lpA, e0);
        float a0, a1; upk2(e0, a0, a1);
        pe[j][0] = cvt_bf16x2(a1, a0);
        ull e1 = fexp2pk_c(pack2(sc_[j][2] * scale + m10, sc_[j][3] * scale + m11), EC2, ENC2);
        lpB = fadd2(lpB, e1);
        float a2, a3; upk2(e1, a2, a3);
        pe[j][1] = cvt_bf16x2(a3, a2);
    }
    #pragma unroll
    for (int kk = 0; kk < 4; kk++) {
        uint32_t vb[4][2];
        #pragma unroll
        for (int u = 0; u < 2; u++) {
            int r = 16 * kk + l8 + ((lane >> 3) & 1) * 8;
            int c = 16 * u + ((lane >> 4) & 1) * 8;
            uint32_t rr[4];
            ldsm4t(rr, vs_u + (uint32_t)(r * FST + c) * 2);
            vb[2*u][0] = rr[0]; vb[2*u][1] = rr[1];
            vb[2*u+1][0] = rr[2]; vb[2*u+1][1] = rr[3];
        }
        uint32_t ap[4] = { pe[2*kk][0], pe[2*kk][1], pe[2*kk+1][0], pe[2*kk+1][1] };
        #pragma unroll
        for (int j = 0; j < 4; j++) mma_bf16(oc[j], ap, vb[j]);
    }
    float lAlo, lAhi, lBlo, lBhi;
    upk2(lpA, lAlo, lAhi);
    upk2(lpB, lBlo, lBhi);
    float lA = lAlo + lAhi, lB = lBlo + lBhi;
    lA += __shfl_xor_sync(0xffffffffu, lA, 1);
    lA += __shfl_xor_sync(0xffffffffu, lA, 2);
    lB += __shfl_xor_sync(0xffffffffu, lB, 1);
    lB += __shfl_xor_sync(0xffffffffu, lB, 2);
    float invA = 1.0f / lA, invB = 1.0f / lB;
    bf16* oA = out + (size_t)(bw * NW2 + qA) * C_ + h * HD + 2 * t4;
    bf16* oB = out + (size_t)(bw * NW2 + qB) * C_ + h * HD + 2 * t4;
    #pragma unroll
    for (int j = 0; j < 4; j++) {
        if (qA < NW2) *(uint32_t*)(oA + 8 * j) = cvt_bf16x2(oc[j][1] * invA, oc[j][0] * invA);
        if (qB < NW2) *(uint32_t*)(oB + 8 * j) = cvt_bf16x2(oc[j][3] * invB, oc[j][2] * invB);
    }
}

// ====== mma.sync bf16 flash attention (qtile 64); row-sum via ones-MMA =======
__global__ void __launch_bounds__(128) fa_mma_kernel(const bf16* __restrict__ qkv,
                                                     bf16* __restrict__ out) {
    __shared__ bf16 Qs[64 * FST];
    __shared__ bf16 Ks[2][64 * FST];
    __shared__ bf16 Vss[2][64 * FST];
    int tid = threadIdx.x;
    int w = tid >> 5, lane = tid & 31;
    int g = lane >> 2, t4 = lane & 3, l8 = lane & 7;
    int bh = blockIdx.x;
    int b = bh / NH, h = bh % NH;
    int q0 = blockIdx.y * 64;
    const bf16* base = qkv + (size_t)b * L_ * C3;
    uint32_t qs_u = smem_to_u32(Qs);
    uint32_t ks_u[2] = { smem_to_u32(Ks[0]), smem_to_u32(Ks[1]) };
    uint32_t vs_u[2] = { smem_to_u32(Vss[0]), smem_to_u32(Vss[1]) };

    int lr = tid >> 1, lhf = (tid & 1) * 16;
    {
        const uint4* qp = (const uint4*)(base + (size_t)(q0 + lr) * C3 + h * HD + lhf);
        *(uint4*)&Qs[lr * FST + lhf]     = qp[0];
        *(uint4*)&Qs[lr * FST + lhf + 8] = qp[1];
    }
    const bf16* kgp = base + C_     + h * HD + lhf;
    const bf16* vgp = base + 2 * C_ + h * HD + lhf;
    uint4 kr0, kr1, vr0, vr1;
    {
        const uint4* kp = (const uint4*)(kgp + (size_t)lr * C3);
        const uint4* vp = (const uint4*)(vgp + (size_t)lr * C3);
        kr0 = kp[0]; kr1 = kp[1]; vr0 = vp[0]; vr1 = vp[1];
    }
    *(uint4*)&Ks[0][lr * FST + lhf]      = kr0;
    *(uint4*)&Ks[0][lr * FST + lhf + 8]  = kr1;
    *(uint4*)&Vss[0][lr * FST + lhf]     = vr0;
    *(uint4*)&Vss[0][lr * FST + lhf + 8] = vr1;
    __syncthreads();

    uint32_t qa[2][4];
    #pragma unroll
    for (int h2 = 0; h2 < 2; h2++) {
        int r = 16 * w + l8 + ((lane >> 3) & 1) * 8;
        int c = h2 * 16 + ((lane >> 4) & 1) * 8;
        ldsm4(qa[h2], qs_u + (uint32_t)(r * FST + c) * 2);
    }

    float oc[4][4] = {};
    float lsum[4] = {};                       // row sums via ones-MMA
    const uint32_t ONE2 = 0x3F803F80u;        // bf16 {1.0, 1.0}
    uint32_t ones[2] = { ONE2, ONE2 };
    const float CSC = 0.17677669529663687f * 1.4426950408889634f;
    ull C2  = dup2(CSC);
    ull NC2 = dup2(-CSC);
    int p = 0;

    for (int kt = 0; kt < 49; kt++) {
        if (kt < 48) {
            size_t roff = (size_t)((kt + 1) * 64 + lr) * C3;
            const uint4* kp = (const uint4*)(kgp + roff);
            const uint4* vp = (const uint4*)(vgp + roff);
            kr0 = kp[0]; kr1 = kp[1]; vr0 = vp[0]; vr1 = vp[1];
        }
        uint32_t kb[8][2][2];
        #pragma unroll
        for (int u = 0; u < 4; u++) {
            #pragma unroll
            for (int h2 = 0; h2 < 2; h2++) {
                int r = 16 * u + l8 + ((lane >> 4) & 1) * 8;
                int c = 16 * h2 + ((lane >> 3) & 1) * 8;
                uint32_t rr[4];
                ldsm4(rr, ks_u[p] + (uint32_t)(r * FST + c) * 2);
                kb[2*u][h2][0] = rr[0]; kb[2*u][h2][1] = rr[1];
                kb[2*u+1][h2][0] = rr[2]; kb[2*u+1][h2][1] = rr[3];
            }
        }
        float sc_[8][4] = {};
        #pragma unroll
        for (int j = 0; j < 8; j++) {
            mma_bf16(sc_[j], qa[0], kb[j][0]);
            mma_bf16(sc_[j], qa[1], kb[j][1]);
        }
        uint32_t pe[8][2];
        #pragma unroll
        for (int j = 0; j < 8; j++) {
            ull e0 = fexp2pk_c(pack2(sc_[j][0], sc_[j][1]), C2, NC2);
            float a0, a1; upk2(e0, a0, a1);
            pe[j][0] = cvt_bf16x2(a1, a0);
            ull e1 = fexp2pk_c(pack2(sc_[j][2], sc_[j][3]), C2, NC2);
            float a2, a3; upk2(e1, a2, a3);
            pe[j][1] = cvt_bf16x2(a3, a2);
        }
        #pragma unroll
        for (int kk = 0; kk < 4; kk++) {
            uint32_t vb[4][2];
            #pragma unroll
            for (int u = 0; u < 2; u++) {
                int r = 16 * kk + l8 + ((lane >> 3) & 1) * 8;
                int c = 16 * u + ((lane >> 4) & 1) * 8;
                uint32_t rr[4];
                ldsm4t(rr, vs_u[p] + (uint32_t)(r * FST + c) * 2);
                vb[2*u][0] = rr[0]; vb[2*u][1] = rr[1];
                vb[2*u+1][0] = rr[2]; vb[2*u+1][1] = rr[3];
            }
            uint32_t ap[4] = { pe[2*kk][0], pe[2*kk][1], pe[2*kk+1][0], pe[2*kk+1][1] };
            #pragma unroll
            for (int j = 0; j < 4; j++) mma_bf16(oc[j], ap, vb[j]);
            mma_bf16(lsum, ap, ones);         // row sum of P (bf16-consistent)
        }
        if (kt < 48) {
            int q = p ^ 1;
            *(uint4*)&Ks[q][lr * FST + lhf]      = kr0;
            *(uint4*)&Ks[q][lr * FST + lhf + 8]  = kr1;
            *(uint4*)&Vss[q][lr * FST + lhf]     = vr0;
            *(uint4*)&Vss[q][lr * FST + lhf + 8] = vr1;
            __syncthreads();
            p = q;
        }
    }
    float invA = 1.0f / lsum[0], invB = 1.0f / lsum[2];
    int qrA = q0 + 16 * w + g;
    bf16* oA = out + (size_t)(b * L_ + qrA) * C_ + h * HD + 2 * t4;
    bf16* oB = oA + 8 * C_;
    #pragma unroll
    for (int j = 0; j < 4; j++) {
        *(uint32_t*)(oA + 8 * j) = cvt_bf16x2(oc[j][1] * invA, oc[j][0] * invA);
        *(uint32_t*)(oB + 8 * j) = cvt_bf16x2(oc[j][3] * invB, oc[j][2] * invB);
    }
}

// ---------------- launcher ----------------
extern "C" void kernel_launch(void* const* d_in, const int* in_sizes, int n_in,
                              void* d_out, int out_size) {
    const float* x        = (const float*)d_in[0];
    const float* n1_s     = (const float*)d_in[3];
    const float* n1_b     = (const float*)d_in[4];
    const float* qkv_w    = (const float*)d_in[5];
    const float* qkv_b    = (const float*)d_in[6];
    const float* proj_w   = (const float*)d_in[7];
    const float* proj_b   = (const float*)d_in[8];
    const float* ln1_s    = (const float*)d_in[9];
    const float* ln1_b    = (const float*)d_in[10];
    const float* qkv2_w   = (const float*)d_in[11];
    const float* qkv2_b   = (const float*)d_in[12];
    const float* out_w    = (const float*)d_in[13];
    const float* out_b    = (const float*)d_in[14];
    const float* ln2_s    = (const float*)d_in[15];
    const float* ln2_b    = (const float*)d_in[16];
    const float* fc1_w    = (const float*)d_in[17];
    const float* fc1_b    = (const float*)d_in[18];
    const float* fc2_w    = (const float*)d_in[19];
    const float* fc2_b    = (const float*)d_in[20];
    float* out = (float*)d_out;

    bf16 *xw, *qkvw, *attnw, *y, *qkv2, *ao, *h1, *wbf;
    float *x1, *x2;
    cudaGetSymbolAddress((void**)&xw,    g_xw);
    cudaGetSymbolAddress((void**)&qkvw,  g_qkvw);
    cudaGetSymbolAddress((void**)&attnw, g_attnw);
    cudaGetSymbolAddress((void**)&x1,    g_x1);
    cudaGetSymbolAddress((void**)&y,     g_y);
    cudaGetSymbolAddress((void**)&qkv2,  g_qkv2);
    cudaGetSymbolAddress((void**)&ao,    g_ao);
    cudaGetSymbolAddress((void**)&x2,    g_x2);
    cudaGetSymbolAddress((void**)&h1,    g_h1);
    cudaGetSymbolAddress((void**)&wbf,   g_wbf);

    const int MB  = NTOK / 64;   // 196
    const int MB2 = NTOK / 32;   // 392

    ln1_wconv_kernel<<<LN1_BLOCKS + 576, 256>>>(x, n1_s, n1_b, xw,
                                                qkv_w, proj_w, qkv2_w, out_w, fc1_w, fc2_w, wbf,
                                                out, out_size);
    gemm_mma_kernel<0><<<dim3(MB, 3), 128>>>(xw, wbf + W_QKV, qkv_b, qkvw, NTOK, C3, C_);
    win_attn_mma_kernel<<<dim3(BW, NH), 128>>>(qkvw, attnw);
    gemm32_mma_kernel<3><<<MB2, 64>>>(attnw, wbf + W_PROJ, proj_b, x, ln1_s, ln1_b, x1, y, C_);
    gemm_mma_kernel<0><<<dim3(MB, 3), 128>>>(y, wbf + W_QKV2, qkv2_b, qkv2, NTOK, C3, C_);
    fa_mma_kernel<<<dim3(B_ * NH, L_ / 64), 128>>>(qkv2, ao);
    gemm32_mma_kernel<2><<<MB2, 64>>>(ao, wbf + W_OUT, out_b, x1, ln2_s, ln2_b, x2, y, C_);
    gemm_mma_kernel<1><<<dim3(MB, 4), 128>>>(y, wbf + W_FC1, fc1_b, h1, NTOK, C4, C_);
    gemm32_mma_kernel<0><<<MB2, 64>>>(h1, wbf + W_FC2, fc2_b, x2, nullptr, nullptr, out, nullptr, C4);
}